// round 16
// baseline (speedup 1.0000x reference)
#include <cuda_runtime.h>
#include <cuda_bf16.h>
#include <math.h>
#include <stdint.h>

#define D_MODEL 1024
#define K2      2048          // split buffer width: [hi(1024) | lo(1024)]
#define NCH     32            // 1024 k-elems / 32 per chunk (hi+lo interleaved)
#define SEQ     2048
#define NB      2
#define NH      16
#define HD      64
#define BHS     (NB*NH)
#define M_ROWS  (NB*SEQ)      // 4096

// ---------------- scratch (static device globals) ----------------
__device__ __nv_bfloat16 g_Qhi[(size_t)BHS * SEQ * HD];
__device__ __nv_bfloat16 g_Qlo[(size_t)BHS * SEQ * HD];
__device__ __nv_bfloat16 g_Khi[(size_t)BHS * SEQ * HD];
__device__ __nv_bfloat16 g_Klo[(size_t)BHS * SEQ * HD];
__device__ __nv_bfloat16 g_Vhi[(size_t)BHS * SEQ * HD];
__device__ __nv_bfloat16 g_Vlo[(size_t)BHS * SEQ * HD];
__device__ float g_AO[(size_t)NB * SEQ * D_MODEL];
__device__ __nv_bfloat16 g_Xs[(size_t)M_ROWS * K2];   // activation split (reused)
__device__ __nv_bfloat16 g_Ws[(size_t)D_MODEL * K2];  // weight split (reused)

// ---------------- helpers ----------------
__device__ __forceinline__ uint32_t smem_u32(const void* p) {
    uint32_t a;
    asm("{ .reg .u64 t; cvta.to.shared.u64 t, %1; cvt.u32.u64 %0, t; }" : "=r"(a) : "l"(p));
    return a;
}
#define SWZ128(x) ((x) ^ (((x) >> 3) & 0x70))

#define CPASYNC16(dst, src) \
    asm volatile("cp.async.cg.shared.global [%0], [%1], 16;" :: "r"(dst), "l"(src) : "memory")
#define CPCOMMIT() asm volatile("cp.async.commit_group;" ::: "memory")
#define CPWAIT1()  asm volatile("cp.async.wait_group 1;" ::: "memory")

#define LDSM_X4(r0, r1, r2, r3, addr) \
    asm volatile("ldmatrix.sync.aligned.m8n8.x4.shared.b16 {%0,%1,%2,%3}, [%4];" \
        : "=r"(r0), "=r"(r1), "=r"(r2), "=r"(r3) : "r"(addr))
#define LDSM_X4T(r0, r1, r2, r3, addr) \
    asm volatile("ldmatrix.sync.aligned.m8n8.x4.trans.shared.b16 {%0,%1,%2,%3}, [%4];" \
        : "=r"(r0), "=r"(r1), "=r"(r2), "=r"(r3) : "r"(addr))

#define MMA16816(d, a, b0, b1) \
    asm volatile("mma.sync.aligned.m16n8k16.row.col.f32.bf16.bf16.f32 " \
        "{%0,%1,%2,%3}, {%4,%5,%6,%7}, {%8,%9}, {%0,%1,%2,%3};" \
        : "+f"((d)[0]), "+f"((d)[1]), "+f"((d)[2]), "+f"((d)[3]) \
        : "r"((a)[0]), "r"((a)[1]), "r"((a)[2]), "r"((a)[3]), "r"(b0), "r"(b1))

__device__ __forceinline__ uint32_t pack_bf2(float v0, float v1) {
    uint32_t r;
    asm("cvt.rn.bf16x2.f32 %0, %1, %2;" : "=r"(r) : "f"(v1), "f"(v0));
    return r;
}
__device__ __forceinline__ void resid_bf2(uint32_t h, float v0, float v1,
                                          float& r0, float& r1) {
    r0 = v0 - __uint_as_float(h << 16);
    r1 = v1 - __uint_as_float(h & 0xffff0000u);
}

// ---------------- split fp32 -> [hi|lo] bf16 along K ----------------
__global__ __launch_bounds__(256) void split_bf16(const float* __restrict__ x,
                                                  __nv_bfloat16* __restrict__ o,
                                                  int rows)
{
    int idx = blockIdx.x * blockDim.x + threadIdx.x;       // one float4 per thread
    int total = rows * 256;
    if (idx >= total) return;
    int m = idx >> 8;
    int k4 = (idx & 255) * 4;
    float4 v = *(const float4*)(x + (size_t)m * 1024 + k4);
    uint32_t h0 = pack_bf2(v.x, v.y), h1 = pack_bf2(v.z, v.w);
    float r0, r1, r2, r3;
    resid_bf2(h0, v.x, v.y, r0, r1);
    resid_bf2(h1, v.z, v.w, r2, r3);
    uint32_t* ph = (uint32_t*)(o + (size_t)m * K2 + k4);
    ph[0] = h0; ph[1] = h1;
    uint32_t* pl = (uint32_t*)(o + (size_t)m * K2 + 1024 + k4);
    pl[0] = pack_bf2(r0, r1); pl[1] = pack_bf2(r2, r3);
}

// ---------------- HMMA GEMM: out = A@B^T + bias (3-term hi/lo) ----------------
// Per 32-element k-chunk, smem row = [hi 64B | lo 64B] for A and B.
// Each chunk loaded ONCE; three term passes: Ahi*Bhi + Alo*Bhi + Ahi*Blo.
// 2-stage / 64 KB smem + launch_bounds(256,2): 2 CTAs/SM (R13 proven config).
#define STAGE_BYTES 32768               // A 16KB + B 16KB
#define GEMM_SMEM   (2 * STAGE_BYTES)   // 64 KB

__global__ __launch_bounds__(256, 2) void gemm_mma(const __nv_bfloat16* __restrict__ A,
                                                   const __nv_bfloat16* __restrict__ B,
                                                   const float* __restrict__ bias,
                                                   float* __restrict__ outF,
                                                   __nv_bfloat16* __restrict__ outHi,
                                                   __nv_bfloat16* __restrict__ outLo,
                                                   int mode)
{
    extern __shared__ char smem[];
    const uint32_t sbase = smem_u32(smem);
    const int tid  = threadIdx.x;
    const int wid  = tid >> 5;
    const int lane = tid & 31;
    const int bm = blockIdx.y * 128;
    const int bn = blockIdx.x * 128;
    const int wm = wid & 3;
    const int wn = wid >> 2;

    // load chunk ic (k0 = ic*32 elems): A+B, hi and lo halves interleaved per row
    auto load_chunk = [&](int ic, int st) {
        const int k0 = ic * 32;
        const uint32_t dst0 = sbase + st * STAGE_BYTES;
#pragma unroll
        for (int j = 0; j < 8; j++) {
            int li  = tid + j * 256;           // 0..2047
            int isB = li >> 10;                // A then B
            int rem = li & 1023;
            int row = rem >> 3;                // 0..127
            int seg = rem & 7;                 // 0..3 hi, 4..7 lo
            const char* srcBase = isB ? (const char*)B : (const char*)A;
            int mrow = (isB ? bn : bm) + row;
            size_t sb = ((size_t)mrow * K2 + k0 + ((seg & 4) ? 1024 : 0)) * 2
                        + (seg & 3) * 16;
            CPASYNC16(dst0 + isB * 16384 + SWZ128(row * 128 + seg * 16), srcBase + sb);
        }
    };

    const int lane8 = lane & 7;
    const int grp   = lane >> 3;
    int aOff[2], bOff[4];
#pragma unroll
    for (int i = 0; i < 2; i++)
        aOff[i] = (wm * 32 + i * 16 + (grp & 1) * 8 + lane8) * 128 + (grp >> 1) * 16;
#pragma unroll
    for (int j = 0; j < 4; j++)
        bOff[j] = (wn * 64 + j * 16 + (grp >> 1) * 8 + lane8) * 128 + (grp & 1) * 16;

    float acc[2][8][4];
#pragma unroll
    for (int i = 0; i < 2; i++)
#pragma unroll
        for (int j = 0; j < 8; j++)
#pragma unroll
            for (int q = 0; q < 4; q++) acc[i][j][q] = 0.f;

    load_chunk(0, 0); CPCOMMIT();
    load_chunk(1, 1); CPCOMMIT();

    for (int ic = 0; ic < NCH; ic++) {
        const int st = ic & 1;
        CPWAIT1();
        __syncthreads();
        const uint32_t sA = sbase + st * STAGE_BYTES;
        const uint32_t sB = sA + 16384;
#pragma unroll
        for (int ks = 0; ks < 2; ks++) {       // 2 x k16 within the 32-elem chunk
            uint32_t ah[2][4], al[2][4];
#pragma unroll
            for (int i = 0; i < 2; i++) {
                LDSM_X4(ah[i][0], ah[i][1], ah[i][2], ah[i][3],
                        sA + SWZ128(aOff[i] + ks * 32));
                LDSM_X4(al[i][0], al[i][1], al[i][2], al[i][3],
                        sA + SWZ128(aOff[i] + 64 + ks * 32));
            }
#pragma unroll
            for (int j = 0; j < 4; j++) {
                uint32_t bh[4], bl[4];
                LDSM_X4(bh[0], bh[1], bh[2], bh[3],
                        sB + SWZ128(bOff[j] + ks * 32));
                LDSM_X4(bl[0], bl[1], bl[2], bl[3],
                        sB + SWZ128(bOff[j] + 64 + ks * 32));
#pragma unroll
                for (int i = 0; i < 2; i++) {  // hi*hi
                    MMA16816(acc[i][2 * j + 0], ah[i], bh[0], bh[1]);
                    MMA16816(acc[i][2 * j + 1], ah[i], bh[2], bh[3]);
                }
#pragma unroll
                for (int i = 0; i < 2; i++) {  // lo*hi
                    MMA16816(acc[i][2 * j + 0], al[i], bh[0], bh[1]);
                    MMA16816(acc[i][2 * j + 1], al[i], bh[2], bh[3]);
                }
#pragma unroll
                for (int i = 0; i < 2; i++) {  // hi*lo
                    MMA16816(acc[i][2 * j + 0], ah[i], bl[0], bl[1]);
                    MMA16816(acc[i][2 * j + 1], ah[i], bl[2], bl[3]);
                }
            }
        }
        __syncthreads();
        if (ic + 2 < NCH) load_chunk(ic + 2, st);
        CPCOMMIT();
    }

    const int r   = lane >> 2;
    const int cp2 = (lane & 3) * 2;
    const float scl = (mode == 1) ? 0.125f : 1.f;
#pragma unroll
    for (int i = 0; i < 2; i++) {
        int m0 = bm + wm * 32 + i * 16 + r;
#pragma unroll
        for (int j = 0; j < 8; j++) {
            int n = bn + wn * 64 + j * 8 + cp2;
            float b0 = bias[n], b1 = bias[n + 1];
            float v0 = acc[i][j][0] + b0, v1 = acc[i][j][1] + b1;
            float v2 = acc[i][j][2] + b0, v3 = acc[i][j][3] + b1;
            if (mode == 0) {
                *(float2*)(outF + (size_t)m0 * D_MODEL + n)       = make_float2(v0, v1);
                *(float2*)(outF + (size_t)(m0 + 8) * D_MODEL + n) = make_float2(v2, v3);
            } else {
                v0 *= scl; v1 *= scl; v2 *= scl; v3 *= scl;
                int bb = m0 >> 11, h = n >> 6, d = n & (HD - 1);
                int s0 = m0 & (SEQ - 1);
                size_t base = ((size_t)(bb * NH + h) * SEQ + s0) * HD + d;
                uint32_t h0 = pack_bf2(v0, v1);
                float r0, r1; resid_bf2(h0, v0, v1, r0, r1);
                *(uint32_t*)(outHi + base) = h0;
                *(uint32_t*)(outLo + base) = pack_bf2(r0, r1);
                uint32_t h1 = pack_bf2(v2, v3);
                float r2, r3; resid_bf2(h1, v2, v3, r2, r3);
                *(uint32_t*)(outHi + base + 8 * HD) = h1;
                *(uint32_t*)(outLo + base + 8 * HD) = pack_bf2(r2, r3);
            }
        }
    }
}

// ---------------------------------------------------------------------------
// HMMA flash attention (unchanged from 626.7us best; fp32 AO epilogue).
// ---------------------------------------------------------------------------
#define SQ_HI   0
#define SQ_LO   16384
#define SKV     32768
#define KVSTAGE 65536                   // Khi|Klo|Vhi|Vlo (16KB each, 128 keys)
#define ATTN_SMEM (SKV + 2 * KVSTAGE)   // 160 KB

__global__ __launch_bounds__(256) void attn_mma()
{
    extern __shared__ char smem[];
    const uint32_t sbase = smem_u32(smem);
    const int tid  = threadIdx.x;
    const int wid  = tid >> 5;
    const int lane = tid & 31;
    const int bh    = blockIdx.y;
    const int qbase = blockIdx.x * 128;
    const size_t qoff = ((size_t)bh * SEQ + qbase) * HD;

    {
        const char* qh = (const char*)(g_Qhi) + qoff * 2;
        const char* ql = (const char*)(g_Qlo) + qoff * 2;
#pragma unroll
        for (int j = 0; j < 4; j++) {
            int li = tid + j * 256;
            int row = li >> 3;
            int cb  = (li & 7) * 16;
            uint32_t so = SWZ128(row * 128 + cb);
            CPASYNC16(sbase + SQ_HI + so, qh + row * 128 + cb);
            CPASYNC16(sbase + SQ_LO + so, ql + row * 128 + cb);
        }
    }
    auto load_kv = [&](int kt, int st) {
        const size_t go = ((size_t)bh * SEQ + kt * 128) * HD * 2;
        const uint32_t base = sbase + SKV + st * KVSTAGE;
#pragma unroll
        for (int j = 0; j < 4; j++) {
            int li = tid + j * 256;
            int row = li >> 3;
            int cb  = (li & 7) * 16;
            uint32_t so = SWZ128(row * 128 + cb);
            size_t g = go + row * 128 + cb;
            CPASYNC16(base + so,         (const char*)g_Khi + g);
            CPASYNC16(base + 16384 + so, (const char*)g_Klo + g);
            CPASYNC16(base + 32768 + so, (const char*)g_Vhi + g);
            CPASYNC16(base + 49152 + so, (const char*)g_Vlo + g);
        }
    };
    load_kv(0, 0); CPCOMMIT();
    load_kv(1, 1); CPCOMMIT();

    const int lane8 = lane & 7;
    const int grp   = lane >> 3;
    const int aOff  = (wid * 16 + (grp & 1) * 8 + lane8) * 128 + (grp >> 1) * 16;
    const int bRowC = (grp >> 1) * 8 + lane8;
    const int bColB = (grp & 1) * 16;
    const int vRowC = (grp & 1) * 8 + lane8;
    const int vColB = (grp >> 1) * 16;

    CPWAIT1();
    __syncthreads();
    uint32_t afh[4][4], afl[4][4];
#pragma unroll
    for (int ks = 0; ks < 4; ks++) {
        LDSM_X4(afh[ks][0], afh[ks][1], afh[ks][2], afh[ks][3],
                sbase + SQ_HI + SWZ128(aOff + ks * 32));
        LDSM_X4(afl[ks][0], afl[ks][1], afl[ks][2], afl[ks][3],
                sbase + SQ_LO + SWZ128(aOff + ks * 32));
    }

    float o[8][4];
#pragma unroll
    for (int j = 0; j < 8; j++)
#pragma unroll
        for (int q = 0; q < 4; q++) o[j][q] = 0.f;
    float m0 = -INFINITY, m1 = -INFINITY, l0 = 0.f, l1 = 0.f;

    for (int kt = 0; kt < 16; kt++) {
        CPWAIT1();
        __syncthreads();
        const uint32_t kv = sbase + SKV + (kt & 1) * KVSTAGE;

        float sc[16][4];
#pragma unroll
        for (int t = 0; t < 16; t++)
#pragma unroll
            for (int q = 0; q < 4; q++) sc[t][q] = 0.f;

#pragma unroll
        for (int term = 0; term < 3; term++) {
            const uint32_t bB = kv + ((term == 2) ? 16384 : 0);
#pragma unroll
            for (int ks = 0; ks < 4; ks++) {
                const uint32_t* af = (term == 1) ? afl[ks] : afh[ks];
                uint32_t bfb[2][4];
                LDSM_X4(bfb[0][0], bfb[0][1], bfb[0][2], bfb[0][3],
                        bB + SWZ128((0 * 16 + bRowC) * 128 + bColB + ks * 32));
                LDSM_X4(bfb[1][0], bfb[1][1], bfb[1][2], bfb[1][3],
                        bB + SWZ128((1 * 16 + bRowC) * 128 + bColB + ks * 32));
#pragma unroll
                for (int j = 0; j < 8; j++) {
                    const int cur = j & 1;
                    MMA16816(sc[2 * j + 0], af, bfb[cur][0], bfb[cur][1]);
                    MMA16816(sc[2 * j + 1], af, bfb[cur][2], bfb[cur][3]);
                    if (j + 2 < 8)
                        LDSM_X4(bfb[cur][0], bfb[cur][1], bfb[cur][2], bfb[cur][3],
                                bB + SWZ128(((j + 2) * 16 + bRowC) * 128 + bColB + ks * 32));
                }
            }
        }

        float mx0 = sc[0][0], mx1 = sc[0][2];
#pragma unroll
        for (int t = 0; t < 16; t++) {
            mx0 = fmaxf(mx0, fmaxf(sc[t][0], sc[t][1]));
            mx1 = fmaxf(mx1, fmaxf(sc[t][2], sc[t][3]));
        }
        mx0 = fmaxf(mx0, __shfl_xor_sync(0xffffffffu, mx0, 1));
        mx0 = fmaxf(mx0, __shfl_xor_sync(0xffffffffu, mx0, 2));
        mx1 = fmaxf(mx1, __shfl_xor_sync(0xffffffffu, mx1, 1));
        mx1 = fmaxf(mx1, __shfl_xor_sync(0xffffffffu, mx1, 2));
        float mn0 = fmaxf(m0, mx0), mn1 = fmaxf(m1, mx1);
        float a0 = __expf(m0 - mn0), a1 = __expf(m1 - mn1);
        m0 = mn0; m1 = mn1;
        float s0 = 0.f, s1 = 0.f;
#pragma unroll
        for (int t = 0; t < 16; t++) {
            sc[t][0] = __expf(sc[t][0] - mn0);
            sc[t][1] = __expf(sc[t][1] - mn0);
            sc[t][2] = __expf(sc[t][2] - mn1);
            sc[t][3] = __expf(sc[t][3] - mn1);
            s0 += sc[t][0] + sc[t][1];
            s1 += sc[t][2] + sc[t][3];
        }
        s0 += __shfl_xor_sync(0xffffffffu, s0, 1);
        s0 += __shfl_xor_sync(0xffffffffu, s0, 2);
        s1 += __shfl_xor_sync(0xffffffffu, s1, 1);
        s1 += __shfl_xor_sync(0xffffffffu, s1, 2);
        l0 = l0 * a0 + s0;
        l1 = l1 * a1 + s1;
#pragma unroll
        for (int j = 0; j < 8; j++) {
            o[j][0] *= a0; o[j][1] *= a0;
            o[j][2] *= a1; o[j][3] *= a1;
        }

#pragma unroll
        for (int kk = 0; kk < 8; kk++) {
            uint32_t vh[4][4], vl[4][4];
#pragma unroll
            for (int j = 0; j < 4; j++) {
                uint32_t vaddr = SWZ128((kk * 16 + vRowC) * 128 + j * 32 + vColB);
                LDSM_X4T(vh[j][0], vh[j][1], vh[j][2], vh[j][3], kv + 32768 + vaddr);
                LDSM_X4T(vl[j][0], vl[j][1], vl[j][2], vl[j][3], kv + 49152 + vaddr);
            }
            uint32_t ph[4], pl[4];
            {
                float r0, r1;
                ph[0] = pack_bf2(sc[2*kk][0],   sc[2*kk][1]);
                resid_bf2(ph[0], sc[2*kk][0], sc[2*kk][1], r0, r1);     pl[0] = pack_bf2(r0, r1);
                ph[1] = pack_bf2(sc[2*kk][2],   sc[2*kk][3]);
                resid_bf2(ph[1], sc[2*kk][2], sc[2*kk][3], r0, r1);     pl[1] = pack_bf2(r0, r1);
                ph[2] = pack_bf2(sc[2*kk+1][0], sc[2*kk+1][1]);
                resid_bf2(ph[2], sc[2*kk+1][0], sc[2*kk+1][1], r0, r1); pl[2] = pack_bf2(r0, r1);
                ph[3] = pack_bf2(sc[2*kk+1][2], sc[2*kk+1][3]);
                resid_bf2(ph[3], sc[2*kk+1][2], sc[2*kk+1][3], r0, r1); pl[3] = pack_bf2(r0, r1);
            }
#pragma unroll
            for (int j = 0; j < 4; j++) {
                MMA16816(o[2*j + 0], ph, vh[j][0], vh[j][1]);
                MMA16816(o[2*j + 1], ph, vh[j][2], vh[j][3]);
            }
#pragma unroll
            for (int j = 0; j < 4; j++) {
                MMA16816(o[2*j + 0], pl, vh[j][0], vh[j][1]);
                MMA16816(o[2*j + 1], pl, vh[j][2], vh[j][3]);
            }
#pragma unroll
            for (int j = 0; j < 4; j++) {
                MMA16816(o[2*j + 0], ph, vl[j][0], vl[j][1]);
                MMA16816(o[2*j + 1], ph, vl[j][2], vl[j][3]);
            }
        }

        __syncthreads();
        if (kt + 2 < 16) load_kv(kt + 2, kt & 1);
        CPCOMMIT();
    }

    const int b = bh >> 4, h = bh & 15;
    const int srow = qbase + wid * 16 + (lane >> 2);
    const int cp2  = (lane & 3) * 2;
    const float i0 = 1.f / l0, i1 = 1.f / l1;
    float* d0 = g_AO + ((size_t)b * SEQ + srow) * D_MODEL + h * HD + cp2;
    float* d1 = g_AO + ((size_t)b * SEQ + srow + 8) * D_MODEL + h * HD + cp2;
#pragma unroll
    for (int j = 0; j < 8; j++) {
        *(float2*)(d0 + j * 8) = make_float2(o[j][0] * i0, o[j][1] * i0);
        *(float2*)(d1 + j * 8) = make_float2(o[j][2] * i1, o[j][3] * i1);
    }
}

// ---------------------------------------------------------------------------
extern "C" void kernel_launch(void* const* d_in, const int* in_sizes, int n_in,
                              void* d_out, int out_size)
{
    const float* query = (const float*)d_in[0];
    const float* key   = (const float*)d_in[1];
    const float* value = (const float*)d_in[2];
    const float* Wq    = (const float*)d_in[3];
    const float* bq    = (const float*)d_in[4];
    const float* Wk    = (const float*)d_in[5];
    const float* bk    = (const float*)d_in[6];
    const float* Wv    = (const float*)d_in[7];
    const float* bv    = (const float*)d_in[8];
    const float* Wo    = (const float*)d_in[9];
    const float* bo    = (const float*)d_in[10];
    float* out = (float*)d_out;

    float* AOp;
    __nv_bfloat16 *Xs, *Ws, *qhi, *qlo, *khi, *klo, *vhi, *vlo;
    cudaGetSymbolAddress((void**)&AOp, g_AO);
    cudaGetSymbolAddress((void**)&Xs,  g_Xs);
    cudaGetSymbolAddress((void**)&Ws,  g_Ws);
    cudaGetSymbolAddress((void**)&qhi, g_Qhi);
    cudaGetSymbolAddress((void**)&qlo, g_Qlo);
    cudaGetSymbolAddress((void**)&khi, g_Khi);
    cudaGetSymbolAddress((void**)&klo, g_Klo);
    cudaGetSymbolAddress((void**)&vhi, g_Vhi);
    cudaGetSymbolAddress((void**)&vlo, g_Vlo);

    cudaFuncSetAttribute(gemm_mma, cudaFuncAttributeMaxDynamicSharedMemorySize, GEMM_SMEM);
    cudaFuncSetAttribute(attn_mma, cudaFuncAttributeMaxDynamicSharedMemorySize, ATTN_SMEM);

    dim3 ggrid(D_MODEL / 128, M_ROWS / 128);          // (8, 32)
    const int sx = M_ROWS;
    const int sw = D_MODEL;

    // Q projection (scaled + split)
    split_bf16<<<sw, 256>>>(Wq, Ws, D_MODEL);
    split_bf16<<<sx, 256>>>(query, Xs, M_ROWS);
    gemm_mma<<<ggrid, 256, GEMM_SMEM>>>(Xs, Ws, bq, nullptr, qhi, qlo, 1);
    // K projection (split)
    split_bf16<<<sw, 256>>>(Wk, Ws, D_MODEL);
    split_bf16<<<sx, 256>>>(key, Xs, M_ROWS);
    gemm_mma<<<ggrid, 256, GEMM_SMEM>>>(Xs, Ws, bk, nullptr, khi, klo, 2);
    // V projection (split)
    split_bf16<<<sw, 256>>>(Wv, Ws, D_MODEL);
    split_bf16<<<sx, 256>>>(value, Xs, M_ROWS);
    gemm_mma<<<ggrid, 256, GEMM_SMEM>>>(Xs, Ws, bv, nullptr, vhi, vlo, 2);

    // attention (HMMA)
    attn_mma<<<dim3(SEQ / 128, BHS), 256, ATTN_SMEM>>>();

    // output projection (fp32 out)
    split_bf16<<<sw, 256>>>(Wo, Ws, D_MODEL);
    split_bf16<<<sx, 256>>>(AOp, Xs, M_ROWS);
    gemm_mma<<<ggrid, 256, GEMM_SMEM>>>(Xs, Ws, bo, out, nullptr, nullptr, 0);
}

// round 17
// speedup vs baseline: 1.0598x; 1.0598x over previous
#include <cuda_runtime.h>
#include <cuda_bf16.h>
#include <math.h>
#include <stdint.h>

#define D_MODEL 1024
#define K2      2048          // split buffer width: [hi(1024) | lo(1024)]
#define NCHUNK  48            // 3072 logical K (hi*hi + lo*hi + hi*lo)
#define SEQ     2048
#define NB      2
#define NH      16
#define HD      64
#define BHS     (NB*NH)
#define M_ROWS  (NB*SEQ)      // 4096

// ---------------- scratch (static device globals) ----------------
__device__ __nv_bfloat16 g_Qhi[(size_t)BHS * SEQ * HD];
__device__ __nv_bfloat16 g_Qlo[(size_t)BHS * SEQ * HD];
__device__ __nv_bfloat16 g_Khi[(size_t)BHS * SEQ * HD];
__device__ __nv_bfloat16 g_Klo[(size_t)BHS * SEQ * HD];
__device__ __nv_bfloat16 g_Vhi[(size_t)BHS * SEQ * HD];
__device__ __nv_bfloat16 g_Vlo[(size_t)BHS * SEQ * HD];
__device__ float g_AO[(size_t)NB * SEQ * D_MODEL];
__device__ __nv_bfloat16 g_Xs[(size_t)M_ROWS * K2];   // activation split (reused)
__device__ __nv_bfloat16 g_Ws[(size_t)D_MODEL * K2];  // weight split (reused)

// ---------------- helpers ----------------
__device__ __forceinline__ uint32_t smem_u32(const void* p) {
    uint32_t a;
    asm("{ .reg .u64 t; cvta.to.shared.u64 t, %1; cvt.u32.u64 %0, t; }" : "=r"(a) : "l"(p));
    return a;
}
#define SWZ128(x) ((x) ^ (((x) >> 3) & 0x70))

#define CPASYNC16(dst, src) \
    asm volatile("cp.async.cg.shared.global [%0], [%1], 16;" :: "r"(dst), "l"(src) : "memory")
#define CPCOMMIT() asm volatile("cp.async.commit_group;" ::: "memory")
#define CPWAIT1()  asm volatile("cp.async.wait_group 1;" ::: "memory")

#define LDSM_X4(r0, r1, r2, r3, addr) \
    asm volatile("ldmatrix.sync.aligned.m8n8.x4.shared.b16 {%0,%1,%2,%3}, [%4];" \
        : "=r"(r0), "=r"(r1), "=r"(r2), "=r"(r3) : "r"(addr))
#define LDSM_X4T(r0, r1, r2, r3, addr) \
    asm volatile("ldmatrix.sync.aligned.m8n8.x4.trans.shared.b16 {%0,%1,%2,%3}, [%4];" \
        : "=r"(r0), "=r"(r1), "=r"(r2), "=r"(r3) : "r"(addr))

#define MMA16816(d, a, b0, b1) \
    asm volatile("mma.sync.aligned.m16n8k16.row.col.f32.bf16.bf16.f32 " \
        "{%0,%1,%2,%3}, {%4,%5,%6,%7}, {%8,%9}, {%0,%1,%2,%3};" \
        : "+f"((d)[0]), "+f"((d)[1]), "+f"((d)[2]), "+f"((d)[3]) \
        : "r"((a)[0]), "r"((a)[1]), "r"((a)[2]), "r"((a)[3]), "r"(b0), "r"(b1))

__device__ __forceinline__ uint32_t pack_bf2(float v0, float v1) {
    uint32_t r;
    asm("cvt.rn.bf16x2.f32 %0, %1, %2;" : "=r"(r) : "f"(v1), "f"(v0));
    return r;
}
__device__ __forceinline__ void resid_bf2(uint32_t h, float v0, float v1,
                                          float& r0, float& r1) {
    r0 = v0 - __uint_as_float(h << 16);
    r1 = v1 - __uint_as_float(h & 0xffff0000u);
}

// ---------------- split fp32 -> [hi|lo] bf16 along K ----------------
__device__ __forceinline__ void split_row(const float* __restrict__ src,
                                          __nv_bfloat16* __restrict__ dst,
                                          int m)
{
    int k4 = threadIdx.x * 4;
    float4 v = *(const float4*)(src + (size_t)m * 1024 + k4);
    uint32_t h0 = pack_bf2(v.x, v.y), h1 = pack_bf2(v.z, v.w);
    float r0, r1, r2, r3;
    resid_bf2(h0, v.x, v.y, r0, r1);
    resid_bf2(h1, v.z, v.w, r2, r3);
    uint32_t* ph = (uint32_t*)(dst + (size_t)m * K2 + k4);
    ph[0] = h0; ph[1] = h1;
    uint32_t* pl = (uint32_t*)(dst + (size_t)m * K2 + 1024 + k4);
    pl[0] = pack_bf2(r0, r1); pl[1] = pack_bf2(r2, r3);
}

// fused per-projection split: X (4096 rows) + W (1024 rows) in ONE launch.
// grid.x = 5120, one block per row; still immediately precedes its GEMM.
__global__ __launch_bounds__(256) void split_pair(const float* __restrict__ X,
                                                  __nv_bfloat16* __restrict__ Xo,
                                                  const float* __restrict__ W,
                                                  __nv_bfloat16* __restrict__ Wo)
{
    int m = blockIdx.x;
    if (m < M_ROWS) split_row(X, Xo, m);
    else            split_row(W, Wo, m - M_ROWS);
}

// ---------------- HMMA GEMM: out = A'@B'^T + bias ----------------
// A' = [Ahi | Alo | Ahi] (K=3072), B' = [Bhi | Bhi | Blo].
// R13 config (measured best 626.7us): 2-stage / 64 KB smem +
// launch_bounds(256,2) -> 2 CTAs/SM; cross-CTA overlap hides wave tail.
#define STAGE_BYTES 32768
#define GEMM_SMEM   (2 * STAGE_BYTES)   // 64 KB

__global__ __launch_bounds__(256, 2) void gemm_mma(const __nv_bfloat16* __restrict__ A,
                                                   const __nv_bfloat16* __restrict__ B,
                                                   const float* __restrict__ bias,
                                                   float* __restrict__ outF,
                                                   __nv_bfloat16* __restrict__ outHi,
                                                   __nv_bfloat16* __restrict__ outLo,
                                                   int mode)
{
    extern __shared__ char smem[];
    const uint32_t sbase = smem_u32(smem);
    const int tid  = threadIdx.x;
    const int wid  = tid >> 5;
    const int lane = tid & 31;
    const int bm = blockIdx.y * 128;
    const int bn = blockIdx.x * 128;
    const int wm = wid & 3;
    const int wn = wid >> 2;

    auto load_chunk = [&](int ic, int st) {
        const int ka = (ic < 32) ? ic * 64 : (ic - 32) * 64;
        const int kb = (ic < 16) ? ic * 64
                     : (ic < 32) ? (ic - 16) * 64
                                 : (ic - 32) * 64 + 1024;
        const uint32_t dA = sbase + st * STAGE_BYTES;
        const uint32_t dB = dA + 16384;
#pragma unroll
        for (int j = 0; j < 4; j++) {
            int li  = tid + j * 256;
            int row = li >> 3;
            int cb  = (li & 7) * 16;
            const char* sa = (const char*)A + ((size_t)(bm + row) * K2 + ka) * 2 + cb;
            CPASYNC16(dA + SWZ128(row * 128 + cb), sa);
            const char* sb = (const char*)B + ((size_t)(bn + row) * K2 + kb) * 2 + cb;
            CPASYNC16(dB + SWZ128(row * 128 + cb), sb);
        }
    };

    const int lane8 = lane & 7;
    const int grp   = lane >> 3;
    int aOff[2], bOff[4];
#pragma unroll
    for (int i = 0; i < 2; i++)
        aOff[i] = (wm * 32 + i * 16 + (grp & 1) * 8 + lane8) * 128 + (grp >> 1) * 16;
#pragma unroll
    for (int j = 0; j < 4; j++)
        bOff[j] = (wn * 64 + j * 16 + (grp >> 1) * 8 + lane8) * 128 + (grp & 1) * 16;

    float acc[2][8][4];
#pragma unroll
    for (int i = 0; i < 2; i++)
#pragma unroll
        for (int j = 0; j < 8; j++)
#pragma unroll
            for (int q = 0; q < 4; q++) acc[i][j][q] = 0.f;

    load_chunk(0, 0); CPCOMMIT();
    load_chunk(1, 1); CPCOMMIT();

    for (int ic = 0; ic < NCHUNK; ic++) {
        const int st = ic & 1;
        CPWAIT1();             // chunk ic landed (ic+1 may still be in flight)
        __syncthreads();
        const uint32_t sA = sbase + st * STAGE_BYTES;
        const uint32_t sB = sA + 16384;
#pragma unroll
        for (int ks = 0; ks < 4; ks++) {
            uint32_t af[2][4], bf[4][4];
#pragma unroll
            for (int i = 0; i < 2; i++)
                LDSM_X4(af[i][0], af[i][1], af[i][2], af[i][3],
                        sA + SWZ128(aOff[i] + ks * 32));
#pragma unroll
            for (int j = 0; j < 4; j++)
                LDSM_X4(bf[j][0], bf[j][1], bf[j][2], bf[j][3],
                        sB + SWZ128(bOff[j] + ks * 32));
#pragma unroll
            for (int i = 0; i < 2; i++)
#pragma unroll
                for (int j = 0; j < 4; j++) {
                    MMA16816(acc[i][2 * j + 0], af[i], bf[j][0], bf[j][1]);
                    MMA16816(acc[i][2 * j + 1], af[i], bf[j][2], bf[j][3]);
                }
        }
        __syncthreads();       // all warps done reading stage st before overwrite
        if (ic + 2 < NCHUNK) load_chunk(ic + 2, st);
        CPCOMMIT();            // unconditional: keeps group count uniform
    }

    const int r   = lane >> 2;
    const int cp2 = (lane & 3) * 2;
    const float scl = (mode == 1) ? 0.125f : 1.f;
#pragma unroll
    for (int i = 0; i < 2; i++) {
        int m0 = bm + wm * 32 + i * 16 + r;
#pragma unroll
        for (int j = 0; j < 8; j++) {
            int n = bn + wn * 64 + j * 8 + cp2;
            float b0 = bias[n], b1 = bias[n + 1];
            float v0 = acc[i][j][0] + b0, v1 = acc[i][j][1] + b1;
            float v2 = acc[i][j][2] + b0, v3 = acc[i][j][3] + b1;
            if (mode == 0) {
                *(float2*)(outF + (size_t)m0 * D_MODEL + n)       = make_float2(v0, v1);
                *(float2*)(outF + (size_t)(m0 + 8) * D_MODEL + n) = make_float2(v2, v3);
            } else {
                v0 *= scl; v1 *= scl; v2 *= scl; v3 *= scl;
                int bb = m0 >> 11, h = n >> 6, d = n & (HD - 1);
                int s0 = m0 & (SEQ - 1);
                size_t base = ((size_t)(bb * NH + h) * SEQ + s0) * HD + d;
                uint32_t h0 = pack_bf2(v0, v1);
                float r0, r1; resid_bf2(h0, v0, v1, r0, r1);
                *(uint32_t*)(outHi + base) = h0;
                *(uint32_t*)(outLo + base) = pack_bf2(r0, r1);
                uint32_t h1 = pack_bf2(v2, v3);
                float r2, r3; resid_bf2(h1, v2, v3, r2, r3);
                *(uint32_t*)(outHi + base + 8 * HD) = h1;
                *(uint32_t*)(outLo + base + 8 * HD) = pack_bf2(r2, r3);
            }
        }
    }
}

// ---------------------------------------------------------------------------
// HMMA flash attention (unchanged from 626.7us best; fp32 AO epilogue).
// ---------------------------------------------------------------------------
#define SQ_HI   0
#define SQ_LO   16384
#define SKV     32768
#define KVSTAGE 65536                   // Khi|Klo|Vhi|Vlo (16KB each, 128 keys)
#define ATTN_SMEM (SKV + 2 * KVSTAGE)   // 160 KB

__global__ __launch_bounds__(256) void attn_mma()
{
    extern __shared__ char smem[];
    const uint32_t sbase = smem_u32(smem);
    const int tid  = threadIdx.x;
    const int wid  = tid >> 5;
    const int lane = tid & 31;
    const int bh    = blockIdx.y;
    const int qbase = blockIdx.x * 128;
    const size_t qoff = ((size_t)bh * SEQ + qbase) * HD;

    {
        const char* qh = (const char*)(g_Qhi) + qoff * 2;
        const char* ql = (const char*)(g_Qlo) + qoff * 2;
#pragma unroll
        for (int j = 0; j < 4; j++) {
            int li = tid + j * 256;
            int row = li >> 3;
            int cb  = (li & 7) * 16;
            uint32_t so = SWZ128(row * 128 + cb);
            CPASYNC16(sbase + SQ_HI + so, qh + row * 128 + cb);
            CPASYNC16(sbase + SQ_LO + so, ql + row * 128 + cb);
        }
    }
    auto load_kv = [&](int kt, int st) {
        const size_t go = ((size_t)bh * SEQ + kt * 128) * HD * 2;
        const uint32_t base = sbase + SKV + st * KVSTAGE;
#pragma unroll
        for (int j = 0; j < 4; j++) {
            int li = tid + j * 256;
            int row = li >> 3;
            int cb  = (li & 7) * 16;
            uint32_t so = SWZ128(row * 128 + cb);
            size_t g = go + row * 128 + cb;
            CPASYNC16(base + so,         (const char*)g_Khi + g);
            CPASYNC16(base + 16384 + so, (const char*)g_Klo + g);
            CPASYNC16(base + 32768 + so, (const char*)g_Vhi + g);
            CPASYNC16(base + 49152 + so, (const char*)g_Vlo + g);
        }
    };
    load_kv(0, 0); CPCOMMIT();
    load_kv(1, 1); CPCOMMIT();

    const int lane8 = lane & 7;
    const int grp   = lane >> 3;
    const int aOff  = (wid * 16 + (grp & 1) * 8 + lane8) * 128 + (grp >> 1) * 16;
    const int bRowC = (grp >> 1) * 8 + lane8;
    const int bColB = (grp & 1) * 16;
    const int vRowC = (grp & 1) * 8 + lane8;
    const int vColB = (grp >> 1) * 16;

    CPWAIT1();
    __syncthreads();
    uint32_t afh[4][4], afl[4][4];
#pragma unroll
    for (int ks = 0; ks < 4; ks++) {
        LDSM_X4(afh[ks][0], afh[ks][1], afh[ks][2], afh[ks][3],
                sbase + SQ_HI + SWZ128(aOff + ks * 32));
        LDSM_X4(afl[ks][0], afl[ks][1], afl[ks][2], afl[ks][3],
                sbase + SQ_LO + SWZ128(aOff + ks * 32));
    }

    float o[8][4];
#pragma unroll
    for (int j = 0; j < 8; j++)
#pragma unroll
        for (int q = 0; q < 4; q++) o[j][q] = 0.f;
    float m0 = -INFINITY, m1 = -INFINITY, l0 = 0.f, l1 = 0.f;

    for (int kt = 0; kt < 16; kt++) {
        CPWAIT1();
        __syncthreads();
        const uint32_t kv = sbase + SKV + (kt & 1) * KVSTAGE;

        float sc[16][4];
#pragma unroll
        for (int t = 0; t < 16; t++)
#pragma unroll
            for (int q = 0; q < 4; q++) sc[t][q] = 0.f;

#pragma unroll
        for (int term = 0; term < 3; term++) {
            const uint32_t bB = kv + ((term == 2) ? 16384 : 0);
#pragma unroll
            for (int ks = 0; ks < 4; ks++) {
                const uint32_t* af = (term == 1) ? afl[ks] : afh[ks];
                uint32_t bfb[2][4];
                LDSM_X4(bfb[0][0], bfb[0][1], bfb[0][2], bfb[0][3],
                        bB + SWZ128((0 * 16 + bRowC) * 128 + bColB + ks * 32));
                LDSM_X4(bfb[1][0], bfb[1][1], bfb[1][2], bfb[1][3],
                        bB + SWZ128((1 * 16 + bRowC) * 128 + bColB + ks * 32));
#pragma unroll
                for (int j = 0; j < 8; j++) {
                    const int cur = j & 1;
                    MMA16816(sc[2 * j + 0], af, bfb[cur][0], bfb[cur][1]);
                    MMA16816(sc[2 * j + 1], af, bfb[cur][2], bfb[cur][3]);
                    if (j + 2 < 8)
                        LDSM_X4(bfb[cur][0], bfb[cur][1], bfb[cur][2], bfb[cur][3],
                                bB + SWZ128(((j + 2) * 16 + bRowC) * 128 + bColB + ks * 32));
                }
            }
        }

        float mx0 = sc[0][0], mx1 = sc[0][2];
#pragma unroll
        for (int t = 0; t < 16; t++) {
            mx0 = fmaxf(mx0, fmaxf(sc[t][0], sc[t][1]));
            mx1 = fmaxf(mx1, fmaxf(sc[t][2], sc[t][3]));
        }
        mx0 = fmaxf(mx0, __shfl_xor_sync(0xffffffffu, mx0, 1));
        mx0 = fmaxf(mx0, __shfl_xor_sync(0xffffffffu, mx0, 2));
        mx1 = fmaxf(mx1, __shfl_xor_sync(0xffffffffu, mx1, 1));
        mx1 = fmaxf(mx1, __shfl_xor_sync(0xffffffffu, mx1, 2));
        float mn0 = fmaxf(m0, mx0), mn1 = fmaxf(m1, mx1);
        float a0 = __expf(m0 - mn0), a1 = __expf(m1 - mn1);
        m0 = mn0; m1 = mn1;
        float s0 = 0.f, s1 = 0.f;
#pragma unroll
        for (int t = 0; t < 16; t++) {
            sc[t][0] = __expf(sc[t][0] - mn0);
            sc[t][1] = __expf(sc[t][1] - mn0);
            sc[t][2] = __expf(sc[t][2] - mn1);
            sc[t][3] = __expf(sc[t][3] - mn1);
            s0 += sc[t][0] + sc[t][1];
            s1 += sc[t][2] + sc[t][3];
        }
        s0 += __shfl_xor_sync(0xffffffffu, s0, 1);
        s0 += __shfl_xor_sync(0xffffffffu, s0, 2);
        s1 += __shfl_xor_sync(0xffffffffu, s1, 1);
        s1 += __shfl_xor_sync(0xffffffffu, s1, 2);
        l0 = l0 * a0 + s0;
        l1 = l1 * a1 + s1;
#pragma unroll
        for (int j = 0; j < 8; j++) {
            o[j][0] *= a0; o[j][1] *= a0;
            o[j][2] *= a1; o[j][3] *= a1;
        }

#pragma unroll
        for (int kk = 0; kk < 8; kk++) {
            uint32_t vh[4][4], vl[4][4];
#pragma unroll
            for (int j = 0; j < 4; j++) {
                uint32_t vaddr = SWZ128((kk * 16 + vRowC) * 128 + j * 32 + vColB);
                LDSM_X4T(vh[j][0], vh[j][1], vh[j][2], vh[j][3], kv + 32768 + vaddr);
                LDSM_X4T(vl[j][0], vl[j][1], vl[j][2], vl[j][3], kv + 49152 + vaddr);
            }
            uint32_t ph[4], pl[4];
            {
                float r0, r1;
                ph[0] = pack_bf2(sc[2*kk][0],   sc[2*kk][1]);
                resid_bf2(ph[0], sc[2*kk][0], sc[2*kk][1], r0, r1);     pl[0] = pack_bf2(r0, r1);
                ph[1] = pack_bf2(sc[2*kk][2],   sc[2*kk][3]);
                resid_bf2(ph[1], sc[2*kk][2], sc[2*kk][3], r0, r1);     pl[1] = pack_bf2(r0, r1);
                ph[2] = pack_bf2(sc[2*kk+1][0], sc[2*kk+1][1]);
                resid_bf2(ph[2], sc[2*kk+1][0], sc[2*kk+1][1], r0, r1); pl[2] = pack_bf2(r0, r1);
                ph[3] = pack_bf2(sc[2*kk+1][2], sc[2*kk+1][3]);
                resid_bf2(ph[3], sc[2*kk+1][2], sc[2*kk+1][3], r0, r1); pl[3] = pack_bf2(r0, r1);
            }
#pragma unroll
            for (int j = 0; j < 4; j++) {
                MMA16816(o[2*j + 0], ph, vh[j][0], vh[j][1]);
                MMA16816(o[2*j + 1], ph, vh[j][2], vh[j][3]);
            }
#pragma unroll
            for (int j = 0; j < 4; j++) {
                MMA16816(o[2*j + 0], pl, vh[j][0], vh[j][1]);
                MMA16816(o[2*j + 1], pl, vh[j][2], vh[j][3]);
            }
#pragma unroll
            for (int j = 0; j < 4; j++) {
                MMA16816(o[2*j + 0], ph, vl[j][0], vl[j][1]);
                MMA16816(o[2*j + 1], ph, vl[j][2], vl[j][3]);
            }
        }

        __syncthreads();
        if (kt + 2 < 16) load_kv(kt + 2, kt & 1);
        CPCOMMIT();
    }

    const int b = bh >> 4, h = bh & 15;
    const int srow = qbase + wid * 16 + (lane >> 2);
    const int cp2  = (lane & 3) * 2;
    const float i0 = 1.f / l0, i1 = 1.f / l1;
    float* d0 = g_AO + ((size_t)b * SEQ + srow) * D_MODEL + h * HD + cp2;
    float* d1 = g_AO + ((size_t)b * SEQ + srow + 8) * D_MODEL + h * HD + cp2;
#pragma unroll
    for (int j = 0; j < 8; j++) {
        *(float2*)(d0 + j * 8) = make_float2(o[j][0] * i0, o[j][1] * i0);
        *(float2*)(d1 + j * 8) = make_float2(o[j][2] * i1, o[j][3] * i1);
    }
}

// ---------------------------------------------------------------------------
extern "C" void kernel_launch(void* const* d_in, const int* in_sizes, int n_in,
                              void* d_out, int out_size)
{
    const float* query = (const float*)d_in[0];
    const float* key   = (const float*)d_in[1];
    const float* value = (const float*)d_in[2];
    const float* Wq    = (const float*)d_in[3];
    const float* bq    = (const float*)d_in[4];
    const float* Wk    = (const float*)d_in[5];
    const float* bk    = (const float*)d_in[6];
    const float* Wv    = (const float*)d_in[7];
    const float* bv    = (const float*)d_in[8];
    const float* Wo    = (const float*)d_in[9];
    const float* bo    = (const float*)d_in[10];
    float* out = (float*)d_out;

    float* AOp;
    __nv_bfloat16 *Xs, *Ws, *qhi, *qlo, *khi, *klo, *vhi, *vlo;
    cudaGetSymbolAddress((void**)&AOp, g_AO);
    cudaGetSymbolAddress((void**)&Xs,  g_Xs);
    cudaGetSymbolAddress((void**)&Ws,  g_Ws);
    cudaGetSymbolAddress((void**)&qhi, g_Qhi);
    cudaGetSymbolAddress((void**)&qlo, g_Qlo);
    cudaGetSymbolAddress((void**)&khi, g_Khi);
    cudaGetSymbolAddress((void**)&klo, g_Klo);
    cudaGetSymbolAddress((void**)&vhi, g_Vhi);
    cudaGetSymbolAddress((void**)&vlo, g_Vlo);

    cudaFuncSetAttribute(gemm_mma, cudaFuncAttributeMaxDynamicSharedMemorySize, GEMM_SMEM);
    cudaFuncSetAttribute(attn_mma, cudaFuncAttributeMaxDynamicSharedMemorySize, ATTN_SMEM);

    dim3 ggrid(D_MODEL / 128, M_ROWS / 128);          // (8, 32)
    const int sp = M_ROWS + D_MODEL;                  // 5120 rows: X then W

    // Q projection (scaled + split)
    split_pair<<<sp, 256>>>(query, Xs, Wq, Ws);
    gemm_mma<<<ggrid, 256, GEMM_SMEM>>>(Xs, Ws, bq, nullptr, qhi, qlo, 1);
    // K projection (split)
    split_pair<<<sp, 256>>>(key, Xs, Wk, Ws);
    gemm_mma<<<ggrid, 256, GEMM_SMEM>>>(Xs, Ws, bk, nullptr, khi, klo, 2);
    // V projection (split)
    split_pair<<<sp, 256>>>(value, Xs, Wv, Ws);
    gemm_mma<<<ggrid, 256, GEMM_SMEM>>>(Xs, Ws, bv, nullptr, vhi, vlo, 2);

    // attention (HMMA)
    attn_mma<<<dim3(SEQ / 128, BHS), 256, ATTN_SMEM>>>();

    // output projection (fp32 out)
    split_pair<<<sp, 256>>>(AOp, Xs, Wo, Ws);
    gemm_mma<<<ggrid, 256, GEMM_SMEM>>>(Xs, Ws, bo, out, nullptr, nullptr, 0);
}